// round 17
// baseline (speedup 1.0000x reference)
#include <cuda_runtime.h>
#include <cuda_fp16.h>
#include <math.h>

// Problem constants (fixed by the dataset)
#define MAXN 20000
#define NODE_DIM 128
#define EDGE_DIM 64
#define HID 128

// Weight offsets in half scratch
#define OFF_EW1 0            // 320*128
#define OFF_EW2 40960        // 128*128
#define OFF_CW1 57344        // 128*64
#define OFF_NW1 65536        // 256*128
#define OFF_NW2 98304        // 128*128
#define W_TOTAL 114688

// Shared strides (halves): all == 8 (mod 64) halves -> conflict-free ldmatrix
#define SA 72
#define SB 136
#define SC 72

#define TILE_E 256
#define EDGE_THREADS 512
#define EDGE_GRID 152

// Scratch (device globals: no allocation allowed)
__device__ float  g_aggr[(size_t)MAXN * HID];      // segment-summed messages (fp32)
__device__ float  g_cacc[(size_t)MAXN * 3];        // coord update accumulator
__device__ __half g_nf_h[(size_t)MAXN * NODE_DIM]; // node_feat in half
__device__ __half g_ag_h[(size_t)MAXN * HID];      // aggr in half (post-edge)
__device__ __half g_w_h[W_TOTAL];                  // all GEMM weights in half

__device__ __forceinline__ float silu_f(float x) {
    return x / (1.0f + __expf(-x));
}
__device__ __forceinline__ unsigned ssa(const void* p) {
    return (unsigned)__cvta_generic_to_shared(p);
}
__device__ __forceinline__ unsigned pack2(float x, float y) {
    __half2 h = __floats2half2_rn(x, y);
    return *(unsigned*)&h;
}
__device__ __forceinline__ void cp16(unsigned saddr, const void* g) {
    asm volatile("cp.async.ca.shared.global [%0], [%1], 16;" :: "r"(saddr), "l"(g));
}
__device__ __forceinline__ void cp_commit() {
    asm volatile("cp.async.commit_group;");
}
template <int N>
__device__ __forceinline__ void cp_wait() {
    asm volatile("cp.async.wait_group %0;" :: "n"(N));
}
__device__ __forceinline__ void red_v4(float* p, float a, float b, float c, float d) {
    asm volatile("red.global.add.v4.f32 [%0], {%1,%2,%3,%4};"
                 :: "l"(p), "f"(a), "f"(b), "f"(c), "f"(d) : "memory");
}
__device__ __forceinline__ void ldsm_x4(unsigned addr, unsigned& r0, unsigned& r1,
                                        unsigned& r2, unsigned& r3) {
    asm volatile("ldmatrix.sync.aligned.m8n8.x4.shared.b16 {%0,%1,%2,%3}, [%4];"
                 : "=r"(r0), "=r"(r1), "=r"(r2), "=r"(r3) : "r"(addr));
}
__device__ __forceinline__ void ldsm_x4_t(unsigned addr, unsigned& r0, unsigned& r1,
                                          unsigned& r2, unsigned& r3) {
    asm volatile("ldmatrix.sync.aligned.m8n8.x4.trans.shared.b16 {%0,%1,%2,%3}, [%4];"
                 : "=r"(r0), "=r"(r1), "=r"(r2), "=r"(r3) : "r"(addr));
}
__device__ __forceinline__ void mma_f16(float* c, unsigned a0, unsigned a1,
                                        unsigned a2, unsigned a3,
                                        unsigned b0, unsigned b1) {
    asm volatile("mma.sync.aligned.m16n8k16.row.col.f32.f16.f16.f32 "
                 "{%0,%1,%2,%3}, {%4,%5,%6,%7}, {%8,%9}, {%0,%1,%2,%3};"
                 : "+f"(c[0]), "+f"(c[1]), "+f"(c[2]), "+f"(c[3])
                 : "r"(a0), "r"(a1), "r"(a2), "r"(a3), "r"(b0), "r"(b1));
}

// GEMM over one k64 tile: A from smem (ldmatrix), B resident in smem.
template <int NP>
__device__ __forceinline__ void gemm_k64(float (*acc)[4], unsigned a_base, int sa,
                                         unsigned b_base, int sb,
                                         int a_row, int a_koff) {
    #pragma unroll
    for (int ks = 0; ks < 4; ks++) {
        unsigned a0, a1, a2, a3;
        ldsm_x4(a_base + (a_row * sa + ks * 16 + a_koff) * 2, a0, a1, a2, a3);
        #pragma unroll
        for (int p = 0; p < NP; p++) {
            unsigned b0, b1, b2, b3;
            ldsm_x4_t(b_base + ((ks * 16 + a_row) * sb + p * 16 + a_koff) * 2,
                      b0, b1, b2, b3);
            mma_f16(acc[2 * p],     a0, a1, a2, a3, b0, b1);
            mma_f16(acc[2 * p + 1], a0, a1, a2, a3, b2, b3);
        }
    }
}

// GEMM with A in registers (8 k16 fragments), B resident (128 rows, two halves).
template <int NP>
__device__ __forceinline__ void gemm_regA(float (*acc)[4], const unsigned (*af)[4],
                                          unsigned b_buf0, unsigned b_buf1, int sb,
                                          int a_row, int a_koff) {
    #pragma unroll
    for (int j = 0; j < 8; j++) {
        unsigned base = (j < 4) ? b_buf0 : b_buf1;
        int lr = (j & 3) * 16;
        #pragma unroll
        for (int p = 0; p < NP; p++) {
            unsigned b0, b1, b2, b3;
            ldsm_x4_t(base + ((lr + a_row) * sb + p * 16 + a_koff) * 2,
                      b0, b1, b2, b3);
            mma_f16(acc[2 * p],     af[j][0], af[j][1], af[j][2], af[j][3], b0, b1);
            mma_f16(acc[2 * p + 1], af[j][0], af[j][1], af[j][2], af[j][3], b2, b3);
        }
    }
}

// ---------------------------------------------------------------------------
// Prep: zero scratch, convert node_feat + all weights to half
// ---------------------------------------------------------------------------
__global__ void prep_kernel(const float* __restrict__ node_feat,
                            const float* __restrict__ eW1,
                            const float* __restrict__ eW2,
                            const float* __restrict__ cW1,
                            const float* __restrict__ nW1,
                            const float* __restrict__ nW2,
                            int N)
{
    int i = blockIdx.x * blockDim.x + threadIdx.x;
    int nf = N * NODE_DIM;
    if (i < nf) {
        g_aggr[i] = 0.0f;
        g_nf_h[i] = __float2half_rn(node_feat[i]);
    }
    if (i < N * 3) g_cacc[i] = 0.0f;
    if (i < W_TOTAL) {
        float v;
        if      (i < OFF_EW2) v = eW1[i - OFF_EW1];
        else if (i < OFF_CW1) v = eW2[i - OFF_EW2];
        else if (i < OFF_NW1) v = cW1[i - OFF_CW1];
        else if (i < OFF_NW2) v = nW1[i - OFF_NW1];
        else                  v = nW2[i - OFF_NW2];
        g_w_h[i] = __float2half_rn(v);
    }
}

// Convert aggregated messages to half (runs after edge kernel)
__global__ void cvt_aggr_kernel(int n) {
    int i = blockIdx.x * blockDim.x + threadIdx.x;
    if (i < n) g_ag_h[i] = __float2half_rn(g_aggr[i]);
}

// ---------------------------------------------------------------------------
// Persistent edge kernel: one 512-thread block per SM; weights fully resident
// in smem; loops over 256-edge tiles. Per warp: 16 edges x full width,
// layers chained in registers. Only A tiles (gathers+attr) are pipelined.
// smem (halves): W1s[320*SB] | W2s[128*SB] | C1s[128*SC] | As[2][256*SA] | idx
// ---------------------------------------------------------------------------
__global__ __launch_bounds__(EDGE_THREADS, 1)
void edge_kernel(const int*   __restrict__ esrc,
                 const int*   __restrict__ edst,
                 const float* __restrict__ edge_attr,
                 const float* __restrict__ coords,
                 const float* __restrict__ eb1,
                 const float* __restrict__ eb2,
                 const float* __restrict__ cb1,
                 const float* __restrict__ cW2,
                 const float* __restrict__ cb2,
                 int E, int ntiles)
{
    extern __shared__ __half smh[];
    __half* W1s = smh;                        // 320 x 136
    __half* W2s = W1s + 320 * SB;             // 128 x 136
    __half* C1s = W2s + 128 * SB;             // 128 x 72
    __half* As  = C1s + 128 * SC;             // 2 x 256 x 72
    int* sidx = (int*)(As + 2 * 256 * SA);    // 256
    int* didx = sidx + 256;                   // 256

    const int tid  = threadIdx.x;
    const int lane = tid & 31;
    const int wid  = tid >> 5;
    const int g    = lane >> 2;
    const int tig  = lane & 3;
    const int RW   = wid * 16;                // warp's 16 rows (0..240)

    const unsigned W1s_b = ssa(W1s);
    const unsigned W2s_b = ssa(W2s);
    const unsigned C1s_b = ssa(C1s);
    const unsigned As_b  = ssa(As);
    const int a_row  = lane & 15;
    const int a_koff = (lane >> 4) * 8;

    // ---- load ALL edge-path weights once (one cp.async group) ----
    #pragma unroll
    for (int q = 0; q < 10; q++) {            // eW1: 320x128 halves -> 5120 cp16
        int i = tid + q * EDGE_THREADS;
        int k = i >> 4, v = i & 15;
        cp16(W1s_b + (k * SB + v * 8) * 2, &g_w_h[OFF_EW1 + (size_t)k * 128 + v * 8]);
    }
    #pragma unroll
    for (int q = 0; q < 4; q++) {             // eW2: 128x128 halves -> 2048 cp16
        int i = tid + q * EDGE_THREADS;
        int k = i >> 4, v = i & 15;
        cp16(W2s_b + (k * SB + v * 8) * 2, &g_w_h[OFF_EW2 + (size_t)k * 128 + v * 8]);
    }
    #pragma unroll
    for (int q = 0; q < 2; q++) {             // cW1: 128x64 halves -> 1024 cp16
        int i = tid + q * EDGE_THREADS;
        int k = i >> 3, v = i & 7;
        cp16(C1s_b + (k * SC + v * 8) * 2, &g_w_h[OFF_CW1 + (size_t)k * 64 + v * 8]);
    }
    cp_commit();                              // G_W

    const unsigned aw0 = As_b + RW * SA * 2;
    const unsigned aw1 = As_b + (256 * SA + RW * SA) * 2;

    // A tile issue: 256 rows x 64 halves -> 2048 cp16 (4 per thread)
    #define ISSUE_A(IDXP, CB, BUF) do {                                      \
        unsigned dstb = As_b + (BUF) * 256 * SA * 2;                         \
        _Pragma("unroll")                                                    \
        for (int q = 0; q < 4; q++) {                                        \
            int i = tid + q * EDGE_THREADS;                                  \
            int e = i >> 3, v = i & 7;                                       \
            cp16(dstb + (e * SA + v * 8) * 2,                                \
                 &g_nf_h[(size_t)(IDXP)[e] * 128 + (CB) + v * 8]);           \
        }                                                                    \
    } while (0)

    for (int tile = blockIdx.x; tile < ntiles; tile += gridDim.x) {
        const int e0 = tile * TILE_E;

        __syncthreads();   // protect idx + As from previous iteration readers
        {
            int e = e0 + (tid & 255); if (e >= E) e = E - 1;
            if (tid < 256) sidx[tid] = esrc[e];
            else           didx[tid - 256] = edst[e];
        }
        __syncthreads();

        // prologue: T0 (src lo) -> b0, T1 (src hi) -> b1
        ISSUE_A(sidx, 0, 0);  cp_commit();
        ISSUE_A(sidx, 64, 1); cp_commit();

        float acc[16][4];
        #pragma unroll
        for (int n = 0; n < 16; n++)
            #pragma unroll
            for (int j = 0; j < 4; j++) acc[n][j] = 0.0f;

        // t=0 (src lo vs W1 rows 0-63)
        cp_wait<1>(); __syncthreads();
        gemm_k64<8>(acc, aw0, SA, W1s_b, SB, a_row, a_koff);
        __syncthreads();
        ISSUE_A(didx, 0, 0); cp_commit();     // T2 (dst lo)
        // t=1 (src hi)
        cp_wait<1>(); __syncthreads();
        gemm_k64<8>(acc, aw1, SA, W1s_b + 64 * SB * 2, SB, a_row, a_koff);
        __syncthreads();
        ISSUE_A(didx, 64, 1); cp_commit();    // T3 (dst hi)
        // t=2 (dst lo)
        cp_wait<1>(); __syncthreads();
        gemm_k64<8>(acc, aw0, SA, W1s_b + 128 * SB * 2, SB, a_row, a_koff);
        __syncthreads();
        // attr tile: plain ld + cvt + sts into b0
        #pragma unroll
        for (int q = 0; q < 8; q++) {
            int i = tid + q * EDGE_THREADS;
            int e = i >> 4, v = i & 15;
            int ee = e0 + e; if (ee >= E) ee = E - 1;
            float4 f = *(const float4*)&edge_attr[(size_t)ee * 64 + v * 4];
            *(__half2*)&As[e * SA + v * 4]     = __floats2half2_rn(f.x, f.y);
            *(__half2*)&As[e * SA + v * 4 + 2] = __floats2half2_rn(f.z, f.w);
        }
        // t=3 (dst hi); the sync also publishes the attr stores
        cp_wait<0>(); __syncthreads();
        gemm_k64<8>(acc, aw1, SA, W1s_b + 192 * SB * 2, SB, a_row, a_koff);
        __syncthreads();
        // t=4 (attr)
        gemm_k64<8>(acc, aw0, SA, W1s_b + 256 * SB * 2, SB, a_row, a_koff);

        // ---- pack h1 = silu(acc + eb1) into layer-2 A fragments ----
        unsigned ah[8][4];
        #pragma unroll
        for (int j = 0; j < 8; j++) {
            int c0 = 16 * j + 2 * tig;
            int c1 = c0 + 8;
            float b00 = eb1[c0], b01 = eb1[c0 + 1];
            float b10 = eb1[c1], b11 = eb1[c1 + 1];
            ah[j][0] = pack2(silu_f(acc[2*j][0] + b00),   silu_f(acc[2*j][1] + b01));
            ah[j][1] = pack2(silu_f(acc[2*j][2] + b00),   silu_f(acc[2*j][3] + b01));
            ah[j][2] = pack2(silu_f(acc[2*j+1][0] + b10), silu_f(acc[2*j+1][1] + b11));
            ah[j][3] = pack2(silu_f(acc[2*j+1][2] + b10), silu_f(acc[2*j+1][3] + b11));
        }

        // ---- layer 2: acc2 = h1 @ eW2 (B resident in W2s; no syncs) ----
        float acc2[16][4];
        #pragma unroll
        for (int n = 0; n < 16; n++)
            #pragma unroll
            for (int j = 0; j < 4; j++) acc2[n][j] = 0.0f;
        gemm_regA<8>(acc2, ah, W2s_b, W2s_b + 64 * SB * 2, SB, a_row, a_koff);

        // ---- m = silu(acc2 + eb2): coord-A frags + vectorized red scatter ----
        unsigned am[8][4];
        const int r0 = RW + g, r1 = RW + g + 8;
        const bool ok0 = (e0 + r0) < E, ok1 = (e0 + r1) < E;
        const int d0 = didx[r0], d1 = didx[r1];
        const int odd = tig & 1;
        const int cbase_off = 2 * tig + (odd ? 6 : 0);
        float* rowp0 = &g_aggr[(size_t)d0 * 128];
        float* rowp1 = &g_aggr[(size_t)d1 * 128];
        #pragma unroll
        for (int j = 0; j < 8; j++) {
            int c0 = 16 * j + 2 * tig;
            int c1 = c0 + 8;
            float b00 = eb2[c0], b01 = eb2[c0 + 1];
            float b10 = eb2[c1], b11 = eb2[c1 + 1];
            float m00 = silu_f(acc2[2*j][0] + b00),   m01 = silu_f(acc2[2*j][1] + b01);
            float m10 = silu_f(acc2[2*j][2] + b00),   m11 = silu_f(acc2[2*j][3] + b01);
            float m20 = silu_f(acc2[2*j+1][0] + b10), m21 = silu_f(acc2[2*j+1][1] + b11);
            float m30 = silu_f(acc2[2*j+1][2] + b10), m31 = silu_f(acc2[2*j+1][3] + b11);
            am[j][0] = pack2(m00, m01);
            am[j][1] = pack2(m10, m11);
            am[j][2] = pack2(m20, m21);
            am[j][3] = pack2(m30, m31);

            int col = 16 * j + cbase_off;
            {
                float sx = odd ? m00 : m20;
                float sy = odd ? m01 : m21;
                float rx = __shfl_xor_sync(0xffffffffu, sx, 1);
                float ry = __shfl_xor_sync(0xffffffffu, sy, 1);
                float v0 = odd ? rx : m00, v1 = odd ? ry : m01;
                float v2 = odd ? m20 : rx, v3 = odd ? m21 : ry;
                if (ok0) red_v4(rowp0 + col, v0, v1, v2, v3);
            }
            {
                float sx = odd ? m10 : m30;
                float sy = odd ? m11 : m31;
                float rx = __shfl_xor_sync(0xffffffffu, sx, 1);
                float ry = __shfl_xor_sync(0xffffffffu, sy, 1);
                float v0 = odd ? rx : m10, v1 = odd ? ry : m11;
                float v2 = odd ? m30 : rx, v3 = odd ? m31 : ry;
                if (ok1) red_v4(rowp1 + col, v0, v1, v2, v3);
            }
        }

        // ---- coord MLP L1: acc3 = m @ cW1 (B resident in C1s) ----
        float acc3[8][4];
        #pragma unroll
        for (int n = 0; n < 8; n++)
            #pragma unroll
            for (int j = 0; j < 4; j++) acc3[n][j] = 0.0f;
        gemm_regA<4>(acc3, am, C1s_b, C1s_b + 64 * SC * 2, SC, a_row, a_koff);

        // ---- w = silu(acc3 + cb1) . cW2 + cb2 ; quad reduce ; scatter ----
        float p1 = 0.0f, p2 = 0.0f;
        #pragma unroll
        for (int t = 0; t < 8; t++) {
            int c = 8 * t + 2 * tig;
            float b0 = cb1[c], b1 = cb1[c + 1];
            float w0 = cW2[c], w1 = cW2[c + 1];
            p1 += silu_f(acc3[t][0] + b0) * w0 + silu_f(acc3[t][1] + b1) * w1;
            p2 += silu_f(acc3[t][2] + b0) * w0 + silu_f(acc3[t][3] + b1) * w1;
        }
        p1 += __shfl_xor_sync(0xffffffffu, p1, 1);
        p1 += __shfl_xor_sync(0xffffffffu, p1, 2);
        p2 += __shfl_xor_sync(0xffffffffu, p2, 1);
        p2 += __shfl_xor_sync(0xffffffffu, p2, 2);
        if (tig < 2) {
            int r = (tig == 0) ? r0 : r1;
            float w = ((tig == 0) ? p1 : p2) + cb2[0];
            if (e0 + r < E) {
                int s = sidx[r], d = didx[r];
                float dx = coords[(size_t)s * 3 + 0] - coords[(size_t)d * 3 + 0];
                float dy = coords[(size_t)s * 3 + 1] - coords[(size_t)d * 3 + 1];
                float dz = coords[(size_t)s * 3 + 2] - coords[(size_t)d * 3 + 2];
                float nrm = sqrtf(dx * dx + dy * dy + dz * dz) + 1e-8f;
                float scl = w / nrm;
                atomicAdd(&g_cacc[(size_t)d * 3 + 0], dx * scl);
                atomicAdd(&g_cacc[(size_t)d * 3 + 1], dy * scl);
                atomicAdd(&g_cacc[(size_t)d * 3 + 2], dz * scl);
            }
        }
    }
    #undef ISSUE_A
}

// ---------------------------------------------------------------------------
// Node kernel: 128-node tile; register-chained; cp.async pipeline (unchanged).
// ---------------------------------------------------------------------------
__global__ __launch_bounds__(256, 2)
void node_kernel(const float* __restrict__ node_feat,
                 const float* __restrict__ coords,
                 const float* __restrict__ nb1,
                 const float* __restrict__ nb2,
                 float* __restrict__ out_nodes,
                 float* __restrict__ out_coords,
                 int N)
{
    extern __shared__ __half smh[];
    __half* As  = smh;                        // 2 x 128 x 72
    __half* Bs  = smh + 2 * 128 * SA;         // 2 x 64 x 136
    __half* W2s = Bs + 2 * 64 * SB;           // 2 x 64 x 136

    const int tid  = threadIdx.x;
    const int n0   = blockIdx.x * 128;
    const int lane = tid & 31;
    const int wid  = tid >> 5;
    const int g    = lane >> 2;
    const int tig  = lane & 3;
    const int RW   = wid * 16;

    const unsigned As_b  = ssa(As);
    const unsigned Bs_b  = ssa(Bs);
    const unsigned W2s_b = ssa(W2s);
    const int a_row  = lane & 15;
    const int a_koff = (lane >> 4) * 8;

    #define N_ISSUE_A(T, BUF) do {                                           \
        const __half* src = ((T) < 2) ? g_nf_h : g_ag_h;                     \
        int cb = ((T) & 1) * 64;                                             \
        unsigned dstb = As_b + (BUF) * 128 * SA * 2;                         \
        _Pragma("unroll")                                                    \
        for (int q = 0; q < 4; q++) {                                        \
            int i = tid + q * 256;                                           \
            int e = i >> 3, v = i & 7;                                       \
            int n = n0 + e; if (n >= N) n = N - 1;                           \
            cp16(dstb + (e * SA + v * 8) * 2,                                \
                 &src[(size_t)n * 128 + cb + v * 8]);                        \
        }                                                                    \
    } while (0)

    #define N_ISSUE_B(T, BUF) do {                                           \
        unsigned dstb = Bs_b + (BUF) * 64 * SB * 2;                          \
        _Pragma("unroll")                                                    \
        for (int q = 0; q < 4; q++) {                                        \
            int i = tid + q * 256;                                           \
            int k = i >> 4, v = i & 15;                                      \
            cp16(dstb + (k * SB + v * 8) * 2,                                \
                 &g_w_h[OFF_NW1 + (size_t)((T) * 64 + k) * 128 + v * 8]);    \
        }                                                                    \
    } while (0)

    N_ISSUE_A(0, 0); N_ISSUE_B(0, 0); cp_commit();             // T0
    #pragma unroll
    for (int q = 0; q < 8; q++) {                              // W2 (nW2)
        int i = tid + q * 256;
        int jj = i >> 10, i2 = i & 1023;
        int k = i2 >> 4, v = i2 & 15;
        cp16(W2s_b + (jj * 64 * SB + k * SB + v * 8) * 2,
             &g_w_h[OFF_NW2 + (size_t)(jj * 64 + k) * 128 + v * 8]);
    }
    cp_commit();                                               // W2

    float acc[16][4];
    #pragma unroll
    for (int n = 0; n < 16; n++)
        #pragma unroll
        for (int j = 0; j < 4; j++) acc[n][j] = 0.0f;

    const unsigned aw0 = As_b + RW * SA * 2;
    const unsigned aw1 = As_b + (128 * SA + RW * SA) * 2;
    const unsigned bb0 = Bs_b;
    const unsigned bb1 = Bs_b + 64 * SB * 2;

    // t=0
    N_ISSUE_A(1, 1); N_ISSUE_B(1, 1); cp_commit();             // T1
    cp_wait<2>(); __syncthreads();
    gemm_k64<8>(acc, aw0, SA, bb0, SB, a_row, a_koff);
    __syncthreads();
    // t=1
    N_ISSUE_A(2, 0); N_ISSUE_B(2, 0); cp_commit();             // T2
    cp_wait<1>(); __syncthreads();
    gemm_k64<8>(acc, aw1, SA, bb1, SB, a_row, a_koff);
    __syncthreads();
    // t=2
    N_ISSUE_A(3, 1); N_ISSUE_B(3, 1); cp_commit();             // T3
    cp_wait<1>(); __syncthreads();
    gemm_k64<8>(acc, aw0, SA, bb0, SB, a_row, a_koff);
    __syncthreads();
    // t=3
    cp_wait<0>(); __syncthreads();
    gemm_k64<8>(acc, aw1, SA, bb1, SB, a_row, a_koff);

    // pack h = silu(acc + nb1) -> layer2 A frags
    unsigned ah[8][4];
    #pragma unroll
    for (int j = 0; j < 8; j++) {
        int c0 = 16 * j + 2 * tig;
        int c1 = c0 + 8;
        float b00 = nb1[c0], b01 = nb1[c0 + 1];
        float b10 = nb1[c1], b11 = nb1[c1 + 1];
        ah[j][0] = pack2(silu_f(acc[2*j][0] + b00),   silu_f(acc[2*j][1] + b01));
        ah[j][1] = pack2(silu_f(acc[2*j][2] + b00),   silu_f(acc[2*j][3] + b01));
        ah[j][2] = pack2(silu_f(acc[2*j+1][0] + b10), silu_f(acc[2*j+1][1] + b11));
        ah[j][3] = pack2(silu_f(acc[2*j+1][2] + b10), silu_f(acc[2*j+1][3] + b11));
    }

    // layer 2: A in regs, B resident in W2s
    float acc2[16][4];
    #pragma unroll
    for (int n = 0; n < 16; n++)
        #pragma unroll
        for (int j = 0; j < 4; j++) acc2[n][j] = 0.0f;
    gemm_regA<8>(acc2, ah, W2s_b, W2s_b + 64 * SB * 2, SB, a_row, a_koff);

    // residual epilogue
    const int r0 = RW + g, r1 = RW + g + 8;
    const int nn0 = n0 + r0, nn1 = n0 + r1;
    #pragma unroll
    for (int j = 0; j < 8; j++) {
        int c0 = 16 * j + 2 * tig;
        int c1 = c0 + 8;
        if (nn0 < N) {
            out_nodes[(size_t)nn0 * 128 + c0] =
                node_feat[(size_t)nn0 * 128 + c0] + acc2[2*j][0] + nb2[c0];
            out_nodes[(size_t)nn0 * 128 + c0 + 1] =
                node_feat[(size_t)nn0 * 128 + c0 + 1] + acc2[2*j][1] + nb2[c0 + 1];
            out_nodes[(size_t)nn0 * 128 + c1] =
                node_feat[(size_t)nn0 * 128 + c1] + acc2[2*j+1][0] + nb2[c1];
            out_nodes[(size_t)nn0 * 128 + c1 + 1] =
                node_feat[(size_t)nn0 * 128 + c1 + 1] + acc2[2*j+1][1] + nb2[c1 + 1];
        }
        if (nn1 < N) {
            out_nodes[(size_t)nn1 * 128 + c0] =
                node_feat[(size_t)nn1 * 128 + c0] + acc2[2*j][2] + nb2[c0];
            out_nodes[(size_t)nn1 * 128 + c0 + 1] =
                node_feat[(size_t)nn1 * 128 + c0 + 1] + acc2[2*j][3] + nb2[c0 + 1];
            out_nodes[(size_t)nn1 * 128 + c1] =
                node_feat[(size_t)nn1 * 128 + c1] + acc2[2*j+1][2] + nb2[c1];
            out_nodes[(size_t)nn1 * 128 + c1 + 1] =
                node_feat[(size_t)nn1 * 128 + c1 + 1] + acc2[2*j+1][3] + nb2[c1 + 1];
        }
    }
    // coords
    for (int i = tid; i < 128 * 3; i += 256) {
        int e = i / 3, d = i % 3;
        int n = n0 + e;
        if (n < N)
            out_coords[(size_t)n * 3 + d] =
                coords[(size_t)n * 3 + d] + g_cacc[(size_t)n * 3 + d];
    }
    #undef N_ISSUE_A
    #undef N_ISSUE_B
}

// ---------------------------------------------------------------------------
extern "C" void kernel_launch(void* const* d_in, const int* in_sizes, int n_in,
                              void* d_out, int out_size)
{
    const float* node_feat = (const float*)d_in[0];
    const int*   eidx      = (const int*)  d_in[1];
    const float* edge_attr = (const float*)d_in[2];
    const float* coords    = (const float*)d_in[3];
    const float* eW1 = (const float*)d_in[4];
    const float* eb1 = (const float*)d_in[5];
    const float* eW2 = (const float*)d_in[6];
    const float* eb2 = (const float*)d_in[7];
    const float* nW1 = (const float*)d_in[8];
    const float* nb1 = (const float*)d_in[9];
    const float* nW2 = (const float*)d_in[10];
    const float* nb2 = (const float*)d_in[11];
    const float* cW1 = (const float*)d_in[12];
    const float* cb1 = (const float*)d_in[13];
    const float* cW2 = (const float*)d_in[14];
    const float* cb2 = (const float*)d_in[15];

    const int N = in_sizes[0] / NODE_DIM;
    const int E = in_sizes[1] / 2;
    const int* esrc = eidx;
    const int* edst = eidx + E;

    float* out_nodes  = (float*)d_out;
    float* out_coords = out_nodes + (size_t)N * NODE_DIM;

    // Edge kernel smem: (320*SB + 128*SB + 128*SC + 2*256*SA) halves + idx
    constexpr int EDGE_SMEM =
        (320 * SB + 128 * SB + 128 * SC + 2 * 256 * SA) * 2 + 512 * 4; // 216,064 B
    constexpr int NODE_SMEM = (2 * 128 * SA + 4 * 64 * SB) * 2;        // 106,496 B
    cudaFuncSetAttribute(edge_kernel, cudaFuncAttributeMaxDynamicSharedMemorySize, EDGE_SMEM);
    cudaFuncSetAttribute(node_kernel, cudaFuncAttributeMaxDynamicSharedMemorySize, NODE_SMEM);

    prep_kernel<<<(N * NODE_DIM + 255) / 256, 256>>>(node_feat, eW1, eW2, cW1, nW1, nW2, N);

    const int ntiles = (E + TILE_E - 1) / TILE_E;
    edge_kernel<<<EDGE_GRID, EDGE_THREADS, EDGE_SMEM>>>(
        esrc, edst, edge_attr, coords, eb1, eb2, cb1, cW2, cb2, E, ntiles);

    cvt_aggr_kernel<<<(N * HID + 255) / 256, 256>>>(N * HID);

    node_kernel<<<(N + 127) / 128, 256, NODE_SMEM>>>(
        node_feat, coords, nb1, nb2, out_nodes, out_coords, N);
}